// round 10
// baseline (speedup 1.0000x reference)
#include <cuda_runtime.h>
#include <cuda_bf16.h>
#include <cstdint>
#include <math.h>

#define B_  4
#define S_  4096
#define D_  64

/* ---------------- SMEM map (bytes) ----------------
   Q tile : [32][72 bf16] hi/lo
   K tile : [128][72 bf16] hi/lo          (E aliases K-hi region)
   E tile : [32][136 bf16] hi/lo
   Vt tile: [64 d][136 bf16] hi/lo                                   */
#define QK_STRIDE 72
#define EV_STRIDE 136
#define SM_LACC  0                      /* 32*4 floats = 512 B  */
#define SM_INVL  512                    /* 32 floats            */
#define SM_QHI   1024
#define SM_QLO   (SM_QHI + 4608)        /* ends 10240 */
#define SM_KHI   10240                  /* 18432 */
#define SM_KLO   (SM_KHI + 18432)       /* ends 47104 */
#define SM_EHI   10240                  /* 8704, aliases K-hi */
#define SM_ELO   19456                  /* 8704, aliases K-hi */
#define SM_VTHI  47104                  /* 17408 */
#define SM_VTLO  (SM_VTHI + 17408)      /* ends 81920 */
#define SMEM_TOTAL 81920                /* 2 CTAs/SM */

#define MMA16816(c, a, b0, b1) \
    asm volatile("mma.sync.aligned.m16n8k16.row.col.f32.bf16.bf16.f32 " \
        "{%0,%1,%2,%3}, {%4,%5,%6,%7}, {%8,%9}, {%0,%1,%2,%3};"         \
        : "+f"((c)[0]), "+f"((c)[1]), "+f"((c)[2]), "+f"((c)[3])        \
        : "r"((a)[0]), "r"((a)[1]), "r"((a)[2]), "r"((a)[3]),           \
          "r"(b0), "r"(b1))

__device__ __forceinline__ void bf16_split2(float f0, float f1,
                                            uint32_t& h2, uint32_t& l2) {
    asm("cvt.rn.bf16x2.f32 %0, %1, %2;" : "=r"(h2) : "f"(f1), "f"(f0));
    float h0 = __uint_as_float(h2 << 16);
    float h1 = __uint_as_float(h2 & 0xFFFF0000u);
    float r0 = f0 - h0, r1 = f1 - h1;
    asm("cvt.rn.bf16x2.f32 %0, %1, %2;" : "=r"(l2) : "f"(r1), "f"(r0));
}

__device__ __forceinline__ float fast_exp(float x) {
    float t = x * 1.4426950408889634f;
    float r = t + 12582912.0f;
    int   n = __float_as_int(r) - 0x4B400000;
    float f = t - (r - 12582912.0f);
    float p = 1.3333558e-3f;
    p = fmaf(p, f, 9.6181291e-3f);
    p = fmaf(p, f, 5.5504109e-2f);
    p = fmaf(p, f, 2.4022651e-1f);
    p = fmaf(p, f, 6.9314718e-1f);
    p = fmaf(p, f, 1.0f);
    return __int_as_float(__float_as_int(p) + (n << 23));
}

/* ------------------------------------------------------------------ */
/* Fused kernel: CTA = (pair p, row-quarter h32, batch b).            */
/* Processes strips qt=p and qt=31-p (33 k-tiles total, uniform).     */
/* Writes normalized W rows (incl. zero upper) and normalized O.      */
/* ------------------------------------------------------------------ */
__global__ void __launch_bounds__(256, 2)
attn_fused(const float* __restrict__ Q, const float* __restrict__ K,
           const float* __restrict__ V, float* __restrict__ outW,
           float* __restrict__ outV, int writeW, int writeV)
{
    extern __shared__ char smx[];
    float* sLacc = (float*)(smx + SM_LACC);
    float* sInv  = (float*)(smx + SM_INVL);

    const int tid = threadIdx.x;
    const int wid = tid >> 5;
    const int lid = tid & 31;
    const int g   = lid >> 2;
    const int tg  = lid & 3;
    const int wr  = wid & 1;    /* 16-row block within 32 */
    const int wc  = wid >> 1;   /* 0..3 */

    const int p   = blockIdx.x;   /* 0..15 */
    const int h32 = blockIdx.y;   /* 0..3  */
    const int b   = blockIdx.z;   /* 0..3  */

#pragma unroll 1
    for (int s = 0; s < 2; s++) {
        const int ss = (p & 1) ? (1 - s) : s;      /* stagger sweep phases */
        const int qt = ss ? (31 - p) : p;
        const int q0 = qt * 128 + 32 * h32;        /* first global q row */

        __syncthreads();                           /* prior strip done with smem */
        if (tid < 128) sLacc[tid] = 0.0f;

        /* ---- load Q (32 rows) split hi/lo ---- */
        const float2* Qb = (const float2*)(Q + ((size_t)b * S_ + q0) * D_);
#pragma unroll
        for (int it = 0; it < 4; it++) {
            const int idx = tid + it * 256;        /* 0..1023 */
            const int row = idx >> 5, cp = idx & 31;
            float2 v = Qb[idx];
            uint32_t h2, l2;
            bf16_split2(v.x, v.y, h2, l2);
            const int soff = (row * QK_STRIDE + 2 * cp) * 2;
            *(uint32_t*)(smx + SM_QHI + soff) = h2;
            *(uint32_t*)(smx + SM_QLO + soff) = l2;
        }

        float o[2][4];
#pragma unroll
        for (int jn = 0; jn < 2; jn++)
#pragma unroll
            for (int r = 0; r < 4; r++) o[jn][r] = 0.0f;

#pragma unroll 1
        for (int kt = 0; kt <= qt; kt++) {
            __syncthreads();    /* prev EV reads done; K/V/E regions writable */

            /* ---- load K tile ---- */
            const float2* Kb = (const float2*)(K + ((size_t)b * S_ + kt * 128) * D_);
#pragma unroll
            for (int it = 0; it < 16; it++) {
                const int idx = tid + it * 256;
                const int row = idx >> 5, cp = idx & 31;
                float2 v = Kb[idx];
                uint32_t h2, l2;
                bf16_split2(v.x, v.y, h2, l2);
                const int soff = (row * QK_STRIDE + 2 * cp) * 2;
                *(uint32_t*)(smx + SM_KHI + soff) = h2;
                *(uint32_t*)(smx + SM_KLO + soff) = l2;
            }
            /* ---- load V tile transposed ---- */
            const float* Vsrc = V + ((size_t)b * S_ + kt * 128) * D_;
#pragma unroll
            for (int it = 0; it < 16; it++) {
                const int idx = tid + it * 256;
                const int kp = idx >> 6, d = idx & 63;
                float v0 = Vsrc[(size_t)(2 * kp) * D_ + d];
                float v1 = Vsrc[(size_t)(2 * kp + 1) * D_ + d];
                uint32_t h2, l2;
                bf16_split2(v0, v1, h2, l2);
                const int soff = (d * EV_STRIDE + 2 * kp) * 2;
                *(uint32_t*)(smx + SM_VTHI + soff) = h2;
                *(uint32_t*)(smx + SM_VTLO + soff) = l2;
            }
            __syncthreads();

            /* ===== QK^T: 32x128, warp tile 16x32 ===== */
            float c[4][4];
#pragma unroll
            for (int j = 0; j < 4; j++)
#pragma unroll
                for (int r = 0; r < 4; r++) c[j][r] = 0.0f;

#pragma unroll
            for (int pp = 0; pp < 3; pp++) {
                const char* Ab = smx + ((pp == 2) ? SM_QLO : SM_QHI);
                const char* Bb = smx + ((pp == 1) ? SM_KLO : SM_KHI);
#pragma unroll
                for (int ks = 0; ks < 4; ks++) {
                    uint32_t a[4];
                    const int base = (16 * wr + g) * QK_STRIDE + 16 * ks + 2 * tg;
                    a[0] = *(const uint32_t*)(Ab + 2 * base);
                    a[1] = *(const uint32_t*)(Ab + 2 * (base + 8 * QK_STRIDE));
                    a[2] = *(const uint32_t*)(Ab + 2 * (base + 8));
                    a[3] = *(const uint32_t*)(Ab + 2 * (base + 8 * QK_STRIDE + 8));
#pragma unroll
                    for (int j = 0; j < 4; j++) {
                        const int cb = (32 * wc + 8 * j + g) * QK_STRIDE + 16 * ks + 2 * tg;
                        uint32_t b0 = *(const uint32_t*)(Bb + 2 * cb);
                        uint32_t b1 = *(const uint32_t*)(Bb + 2 * (cb + 8));
                        MMA16816(c[j], a, b0, b1);
                    }
                }
            }
            __syncthreads();    /* K reads done; E (aliases K-hi) writable */

            /* ===== epilogue: mask+exp, E split, row-sum accumulate ===== */
            const bool diag = (kt == qt);
#pragma unroll
            for (int u = 0; u < 2; u++) {
                const int row = 16 * wr + 8 * u + g;
                float rs = 0.0f;
#pragma unroll
                for (int j = 0; j < 4; j++) {
                    const int cb = 32 * wc + 8 * j + 2 * tg;
                    float s0 = c[j][2 * u]     * 0.125f;
                    float s1 = c[j][2 * u + 1] * 0.125f;
                    float e0 = (diag && (cb     > 32 * h32 + row)) ? 0.0f : fast_exp(s0);
                    float e1 = (diag && (cb + 1 > 32 * h32 + row)) ? 0.0f : fast_exp(s1);
                    rs += e0 + e1;
                    uint32_t h2, l2;
                    bf16_split2(e0, e1, h2, l2);
                    const int eoff = (row * EV_STRIDE + cb) * 2;
                    *(uint32_t*)(smx + SM_EHI + eoff) = h2;
                    *(uint32_t*)(smx + SM_ELO + eoff) = l2;
                }
                rs += __shfl_xor_sync(0xffffffffu, rs, 1);
                rs += __shfl_xor_sync(0xffffffffu, rs, 2);
                if (tg == 0) sLacc[row * 4 + wc] += rs;
            }
            __syncthreads();    /* E visible */

            /* ===== EV accumulate: 32x64, warp tile 16x16 ===== */
            if (writeV) {
#pragma unroll
                for (int pp = 0; pp < 3; pp++) {
                    const char* Ab = smx + ((pp == 2) ? SM_ELO : SM_EHI);
                    const char* Bb = smx + ((pp == 1) ? SM_VTLO : SM_VTHI);
#pragma unroll
                    for (int ks = 0; ks < 8; ks++) {
                        uint32_t a[4];
                        const int base = (16 * wr + g) * EV_STRIDE + 16 * ks + 2 * tg;
                        a[0] = *(const uint32_t*)(Ab + 2 * base);
                        a[1] = *(const uint32_t*)(Ab + 2 * (base + 8 * EV_STRIDE));
                        a[2] = *(const uint32_t*)(Ab + 2 * (base + 8));
                        a[3] = *(const uint32_t*)(Ab + 2 * (base + 8 * EV_STRIDE + 8));
#pragma unroll
                        for (int jn = 0; jn < 2; jn++) {
                            const int cb = (16 * wc + 8 * jn + g) * EV_STRIDE + 16 * ks + 2 * tg;
                            uint32_t b0 = *(const uint32_t*)(Bb + 2 * cb);
                            uint32_t b1 = *(const uint32_t*)(Bb + 2 * (cb + 8));
                            MMA16816(o[jn], a, b0, b1);
                        }
                    }
                }
            }

            /* ---- coalesced unnormalized W tile store ---- */
            if (writeW) {
                float* Wt = outW + ((size_t)(b * S_ + q0)) * S_ + (size_t)kt * 128;
#pragma unroll
                for (int it = 0; it < 4; it++) {
                    const int f   = tid + it * 256;   /* 0..1023 */
                    const int row = f >> 5, c4 = f & 31;
                    const int eo  = (row * EV_STRIDE + 4 * c4) * 2;
                    uint32_t h0 = *(const uint32_t*)(smx + SM_EHI + eo);
                    uint32_t l0 = *(const uint32_t*)(smx + SM_ELO + eo);
                    uint32_t h1 = *(const uint32_t*)(smx + SM_EHI + eo + 4);
                    uint32_t l1 = *(const uint32_t*)(smx + SM_ELO + eo + 4);
                    float4 w;
                    w.x = __uint_as_float(h0 << 16)         + __uint_as_float(l0 << 16);
                    w.y = __uint_as_float(h0 & 0xFFFF0000u) + __uint_as_float(l0 & 0xFFFF0000u);
                    w.z = __uint_as_float(h1 << 16)         + __uint_as_float(l1 << 16);
                    w.w = __uint_as_float(h1 & 0xFFFF0000u) + __uint_as_float(l1 & 0xFFFF0000u);
                    *(float4*)(Wt + (size_t)row * S_ + 4 * c4) = w;
                }
            }
        }   /* kt loop */

        __syncthreads();
        if (tid < 32) {
            float L = sLacc[tid * 4] + sLacc[tid * 4 + 1]
                    + sLacc[tid * 4 + 2] + sLacc[tid * 4 + 3];
            sInv[tid] = 1.0f / L;
        }
        __syncthreads();

        /* ---- normalized O store ---- */
        if (writeV) {
#pragma unroll
            for (int u = 0; u < 2; u++) {
                const int row = 16 * wr + 8 * u + g;
                const float inv = sInv[row];
#pragma unroll
                for (int jn = 0; jn < 2; jn++) {
                    const int col = 16 * wc + 8 * jn + 2 * tg;
                    float2 w;
                    w.x = o[jn][2 * u]     * inv;
                    w.y = o[jn][2 * u + 1] * inv;
                    *(float2*)(outV + ((size_t)(b * S_ + q0 + row)) * D_ + col) = w;
                }
            }
        }

        /* ---- W normalization sweep + upper-triangle zero fill ---- */
        if (writeW) {
            const int nsc = (qt + 1) * 32;     /* scaled float4s per row */
#pragma unroll 1
            for (int it = 0; it < 128; it++) {
                const int f   = tid + it * 256;    /* 0..32767 */
                const int row = f >> 10, c4 = f & 1023;
                float4* ptr = (float4*)(outW + ((size_t)(b * S_ + q0 + row)) * S_) + c4;
                if (c4 < nsc) {
                    const float inv = sInv[row];
                    float4 v = *ptr;
                    v.x *= inv; v.y *= inv; v.z *= inv; v.w *= inv;
                    *ptr = v;
                } else {
                    float4 z; z.x = z.y = z.z = z.w = 0.0f;
                    *ptr = z;
                }
            }
        }
    }   /* strip loop */
}

/* ------------------------------------------------------------------ */
extern "C" void kernel_launch(void* const* d_in, const int* in_sizes, int n_in,
                              void* d_out, int out_size)
{
    const float* Q = (const float*)d_in[0];
    const float* K = (const float*)d_in[1];
    const float* V = (const float*)d_in[2];

    const long long VE = (long long)B_ * S_ * D_;
    const long long WE = (long long)B_ * S_ * S_;

    float* outVec = nullptr;
    float* outW   = nullptr;
    int writeW = 0, writeV = 0;
    if ((long long)out_size == VE + WE) {
        outVec = (float*)d_out;
        outW   = (float*)d_out + VE;
        writeW = 1; writeV = 1;
    } else if ((long long)out_size == WE) {
        outW   = (float*)d_out;
        writeW = 1;
    } else {
        outVec = (float*)d_out;
        writeV = 1;
    }

    cudaFuncSetAttribute(attn_fused, cudaFuncAttributeMaxDynamicSharedMemorySize,
                         SMEM_TOTAL);

    dim3 grid(16, 4, 4);
    attn_fused<<<grid, 256, SMEM_TOTAL>>>(Q, K, V, outW, outVec, writeW, writeV);
}

// round 11
// speedup vs baseline: 1.1465x; 1.1465x over previous
#include <cuda_runtime.h>
#include <cuda_bf16.h>
#include <cstdint>
#include <math.h>

#define B_  4
#define S_  4096
#define D_  64
#define BT  64                     /* unit tile size (q and k) */
#define QT_N   (S_ / BT)           /* 64 */
#define UNITS_PER_B (QT_N * (QT_N + 1) / 2)   /* 2080 */
#define NUNITS (UNITS_PER_B * B_)             /* 8320 */

/* ---------------- scratch ---------------- */
__device__ float g_Lp[(size_t)NUNITS * BT];
__device__ float g_Op[(size_t)NUNITS * BT * D_];
__device__ float g_invL[B_ * S_];

/* ---------------- SMEM map (bytes) ----------------
   all tiles [64 rows][72 bf16], stride 72; E aliases K. */
#define TS 72
#define SM_RSUM  0                  /* 64*2 floats = 512 B */
#define SM_QHI   1024
#define SM_QLO   (SM_QHI + 9216)    /* 10240 */
#define SM_KHI   19456
#define SM_KLO   (SM_KHI + 9216)    /* 28672 */
#define SM_EHI   19456              /* alias K-hi */
#define SM_ELO   28672              /* alias K-lo */
#define SM_VTHI  37888
#define SM_VTLO  (SM_VTHI + 9216)   /* 47104 */
#define SMEM_TOTAL 56320            /* -> 4 CTAs/SM */

#define MMA16816(c, a, b0, b1) \
    asm volatile("mma.sync.aligned.m16n8k16.row.col.f32.bf16.bf16.f32 " \
        "{%0,%1,%2,%3}, {%4,%5,%6,%7}, {%8,%9}, {%0,%1,%2,%3};"         \
        : "+f"((c)[0]), "+f"((c)[1]), "+f"((c)[2]), "+f"((c)[3])        \
        : "r"((a)[0]), "r"((a)[1]), "r"((a)[2]), "r"((a)[3]),           \
          "r"(b0), "r"(b1))

__device__ __forceinline__ void bf16_split2(float f0, float f1,
                                            uint32_t& h2, uint32_t& l2) {
    asm("cvt.rn.bf16x2.f32 %0, %1, %2;" : "=r"(h2) : "f"(f1), "f"(f0));
    float h0 = __uint_as_float(h2 << 16);
    float h1 = __uint_as_float(h2 & 0xFFFF0000u);
    float r0 = f0 - h0, r1 = f1 - h1;
    asm("cvt.rn.bf16x2.f32 %0, %1, %2;" : "=r"(l2) : "f"(r1), "f"(r0));
}

__device__ __forceinline__ float fast_exp(float x) {
    float t = x * 1.4426950408889634f;
    float r = t + 12582912.0f;
    int   n = __float_as_int(r) - 0x4B400000;
    float f = t - (r - 12582912.0f);
    float p = 1.3333558e-3f;
    p = fmaf(p, f, 9.6181291e-3f);
    p = fmaf(p, f, 5.5504109e-2f);
    p = fmaf(p, f, 2.4022651e-1f);
    p = fmaf(p, f, 6.9314718e-1f);
    p = fmaf(p, f, 1.0f);
    return __int_as_float(__float_as_int(p) + (n << 23));
}

/* ------------------------------------------------------------------ */
/* Kernel A: one (qt,kt) 64x64 unit per CTA; 256 thr; 4 CTAs/SM.      */
/* ------------------------------------------------------------------ */
__global__ void __launch_bounds__(256, 4)
attn_tiles(const float* __restrict__ Q, const float* __restrict__ K,
           const float* __restrict__ V, float* __restrict__ outW,
           int writeW)
{
    extern __shared__ char smx[];

    const int tid = threadIdx.x;
    const int wid = tid >> 5;
    const int lid = tid & 31;
    const int g   = lid >> 2;
    const int tg  = lid & 3;
    const int wr  = wid & 3;    /* 16-row block: 0..3  */
    const int wc  = wid >> 2;   /* 32-col half: 0..1   */

    const int b = blockIdx.y;
    const int x = blockIdx.x;
    int qt = (int)((sqrtf(8.0f * (float)x + 1.0f) - 1.0f) * 0.5f);
    while ((qt + 1) * (qt + 2) / 2 <= x) qt++;
    while (qt * (qt + 1) / 2 > x) qt--;
    const int kt   = x - qt * (qt + 1) / 2;
    const int unit = b * UNITS_PER_B + x;
    const bool diag = (qt == kt);

    const float2* Qb = (const float2*)(Q + ((size_t)b * S_ + (size_t)qt * BT) * D_);
    const float2* Kb = (const float2*)(K + ((size_t)b * S_ + (size_t)kt * BT) * D_);
    const float*  Vsrc = V + ((size_t)b * S_ + (size_t)kt * BT) * D_;

    /* ---- load Q,K (64x64 each): split hi/lo, stride 72 ---- */
#pragma unroll
    for (int it = 0; it < 8; it++) {
        const int idx = tid + it * 256;          /* 0..2047 */
        const int row = idx >> 5, cp = idx & 31;
        const int soff = (row * TS + 2 * cp) * 2;
        {
            float2 v = Qb[idx];
            uint32_t h2, l2;
            bf16_split2(v.x, v.y, h2, l2);
            *(uint32_t*)(smx + SM_QHI + soff) = h2;
            *(uint32_t*)(smx + SM_QLO + soff) = l2;
        }
        {
            float2 v = Kb[idx];
            uint32_t h2, l2;
            bf16_split2(v.x, v.y, h2, l2);
            *(uint32_t*)(smx + SM_KHI + soff) = h2;
            *(uint32_t*)(smx + SM_KLO + soff) = l2;
        }
    }
    /* ---- V transpose: Vt[d][k], stride 72, coalesced LDG ---- */
#pragma unroll
    for (int it = 0; it < 8; it++) {
        const int idx = tid + it * 256;          /* 0..2047 */
        const int kp = idx >> 6, d = idx & 63;
        float v0 = Vsrc[(size_t)(2 * kp) * D_ + d];
        float v1 = Vsrc[(size_t)(2 * kp + 1) * D_ + d];
        uint32_t h2, l2;
        bf16_split2(v0, v1, h2, l2);
        const int soff = (d * TS + 2 * kp) * 2;
        *(uint32_t*)(smx + SM_VTHI + soff) = h2;
        *(uint32_t*)(smx + SM_VTLO + soff) = l2;
    }
    __syncthreads();

    /* ================= QK^T: warp tile 16 x 32 ================= */
    float c[4][4];
#pragma unroll
    for (int j = 0; j < 4; j++)
#pragma unroll
        for (int r = 0; r < 4; r++) c[j][r] = 0.0f;

#pragma unroll
    for (int pp = 0; pp < 3; pp++) {
        const char* Ab = smx + ((pp == 2) ? SM_QLO : SM_QHI);
        const char* Bb = smx + ((pp == 1) ? SM_KLO : SM_KHI);
#pragma unroll
        for (int ks = 0; ks < 4; ks++) {
            uint32_t a[4];
            const int base = (16 * wr + g) * TS + 16 * ks + 2 * tg;
            a[0] = *(const uint32_t*)(Ab + 2 * base);
            a[1] = *(const uint32_t*)(Ab + 2 * (base + 8 * TS));
            a[2] = *(const uint32_t*)(Ab + 2 * (base + 8));
            a[3] = *(const uint32_t*)(Ab + 2 * (base + 8 * TS + 8));
#pragma unroll
            for (int j = 0; j < 4; j++) {
                const int cb = (32 * wc + 8 * j + g) * TS + 16 * ks + 2 * tg;
                uint32_t b0 = *(const uint32_t*)(Bb + 2 * cb);
                uint32_t b1 = *(const uint32_t*)(Bb + 2 * (cb + 8));
                MMA16816(c[j], a, b0, b1);
            }
        }
    }
    __syncthreads();   /* K reads done; E (aliases K) writable */

    /* ======== epilogue: mask+exp, E split to smem, row sums ======== */
#pragma unroll
    for (int u = 0; u < 2; u++) {
        const int row = 16 * wr + 8 * u + g;
        float rs = 0.0f;
#pragma unroll
        for (int j = 0; j < 4; j++) {
            const int cb = 32 * wc + 8 * j + 2 * tg;
            float s0 = c[j][2 * u]     * 0.125f;
            float s1 = c[j][2 * u + 1] * 0.125f;
            float e0 = (diag && (cb     > row)) ? 0.0f : fast_exp(s0);
            float e1 = (diag && (cb + 1 > row)) ? 0.0f : fast_exp(s1);
            rs += e0 + e1;
            uint32_t h2, l2;
            bf16_split2(e0, e1, h2, l2);
            const int eoff = (row * TS + cb) * 2;
            *(uint32_t*)(smx + SM_EHI + eoff) = h2;
            *(uint32_t*)(smx + SM_ELO + eoff) = l2;
        }
        rs += __shfl_xor_sync(0xffffffffu, rs, 1);
        rs += __shfl_xor_sync(0xffffffffu, rs, 2);
        if (tg == 0)
            ((float*)(smx + SM_RSUM))[row * 2 + wc] = rs;
    }
    __syncthreads();

    if (tid < BT) {
        const float* r = (const float*)(smx + SM_RSUM);
        g_Lp[(size_t)unit * BT + tid] = r[2 * tid] + r[2 * tid + 1];
    }

    /* ================= O = E @ V: warp tile 16 x 32 ================= */
    float o[4][4];
#pragma unroll
    for (int j = 0; j < 4; j++)
#pragma unroll
        for (int r = 0; r < 4; r++) o[j][r] = 0.0f;

#pragma unroll
    for (int pp = 0; pp < 3; pp++) {
        const char* Ab = smx + ((pp == 2) ? SM_ELO : SM_EHI);
        const char* Bb = smx + ((pp == 1) ? SM_VTLO : SM_VTHI);
#pragma unroll
        for (int ks = 0; ks < 4; ks++) {
            uint32_t a[4];
            const int base = (16 * wr + g) * TS + 16 * ks + 2 * tg;
            a[0] = *(const uint32_t*)(Ab + 2 * base);
            a[1] = *(const uint32_t*)(Ab + 2 * (base + 8 * TS));
            a[2] = *(const uint32_t*)(Ab + 2 * (base + 8));
            a[3] = *(const uint32_t*)(Ab + 2 * (base + 8 * TS + 8));
#pragma unroll
            for (int j = 0; j < 4; j++) {
                const int cb = (32 * wc + 8 * j + g) * TS + 16 * ks + 2 * tg;
                uint32_t b0 = *(const uint32_t*)(Bb + 2 * cb);
                uint32_t b1 = *(const uint32_t*)(Bb + 2 * (cb + 8));
                MMA16816(o[j], a, b0, b1);
            }
        }
    }

    /* ---- coalesced W store: reconstruct e = hi + lo from E smem ---- */
    if (writeW) {
        float* Wt = outW + ((size_t)(b * S_ + qt * BT)) * S_ + (size_t)kt * BT;
#pragma unroll
        for (int it = 0; it < 4; it++) {
            const int f   = tid + it * 256;      /* float4 id: 0..1023 */
            const int row = f >> 4, c4 = f & 15;
            const int eo  = (row * TS + 4 * c4) * 2;
            uint32_t h0 = *(const uint32_t*)(smx + SM_EHI + eo);
            uint32_t l0 = *(const uint32_t*)(smx + SM_ELO + eo);
            uint32_t h1 = *(const uint32_t*)(smx + SM_EHI + eo + 4);
            uint32_t l1 = *(const uint32_t*)(smx + SM_ELO + eo + 4);
            float4 w;
            w.x = __uint_as_float(h0 << 16)         + __uint_as_float(l0 << 16);
            w.y = __uint_as_float(h0 & 0xFFFF0000u) + __uint_as_float(l0 & 0xFFFF0000u);
            w.z = __uint_as_float(h1 << 16)         + __uint_as_float(l1 << 16);
            w.w = __uint_as_float(h1 & 0xFFFF0000u) + __uint_as_float(l1 & 0xFFFF0000u);
            *(float4*)(Wt + (size_t)row * S_ + 4 * c4) = w;
        }
    }

    /* ---- store O partials ---- */
    float* Ob = g_Op + (size_t)unit * (BT * D_);
#pragma unroll
    for (int u = 0; u < 2; u++) {
        const int row = 16 * wr + 8 * u + g;
#pragma unroll
        for (int j = 0; j < 4; j++) {
            const int cb = 32 * wc + 8 * j + 2 * tg;
            float2 w;
            w.x = o[j][2 * u];
            w.y = o[j][2 * u + 1];
            *(float2*)(Ob + (size_t)row * D_ + cb) = w;
        }
    }
}

/* ---------------- Kernel B1: invL per row ---------------- */
__global__ void __launch_bounds__(256)
reduce_l()
{
    int t = blockIdx.x * 256 + threadIdx.x;
    if (t >= B_ * S_) return;
    int b = t >> 12, q = t & (S_ - 1);
    int qt = q >> 6, i = q & (BT - 1);
    int tri = qt * (qt + 1) / 2;
    float s = 0.0f;
    for (int kt = 0; kt <= qt; kt++)
        s += g_Lp[((size_t)(b * UNITS_PER_B + tri + kt)) * BT + i];
    g_invL[t] = 1.0f / s;
}

/* ---------------- Kernel B2: O = (sum of partials) * invL ---------------- */
__global__ void __launch_bounds__(256)
reduce_o(float* __restrict__ outV)
{
    int t = blockIdx.x * 256 + threadIdx.x;
    if (t >= B_ * S_ * (D_ / 4)) return;
    int d4 = t & 15;
    int q  = (t >> 4) & (S_ - 1);
    int b  = t >> 16;
    int qt = q >> 6, i = q & (BT - 1);
    int tri = qt * (qt + 1) / 2;
    float ax = 0.f, ay = 0.f, az = 0.f, aw = 0.f;
    for (int kt = 0; kt <= qt; kt++) {
        const float4 v = *(const float4*)(g_Op +
            ((size_t)(b * UNITS_PER_B + tri + kt) * BT + i) * D_ + d4 * 4);
        ax += v.x; ay += v.y; az += v.z; aw += v.w;
    }
    float inv = g_invL[b * S_ + q];
    float4 r; r.x = ax * inv; r.y = ay * inv; r.z = az * inv; r.w = aw * inv;
    *(float4*)(outV + ((size_t)(b * S_ + q)) * D_ + d4 * 4) = r;
}

/* ---------------- Kernel C: normalize weights + zero upper (64-gran) ---- */
__global__ void __launch_bounds__(256)
norm_w(float* __restrict__ outW)
{
    size_t t = (size_t)blockIdx.x * 256 + threadIdx.x;   /* float4 index */
    int kq = (int)(t & 1023);
    int q  = (int)((t >> 10) & (S_ - 1));
    int b  = (int)(t >> 22);
    float4* p = (float4*)outW + t;
    int k = kq * 4;
    if ((k >> 6) > (q >> 6)) {
        float4 z; z.x = z.y = z.z = z.w = 0.0f;
        *p = z;
    } else {
        float inv = g_invL[b * S_ + q];
        float4 v = *p;
        v.x *= inv; v.y *= inv; v.z *= inv; v.w *= inv;
        *p = v;
    }
}

/* ------------------------------------------------------------------ */
extern "C" void kernel_launch(void* const* d_in, const int* in_sizes, int n_in,
                              void* d_out, int out_size)
{
    const float* Q = (const float*)d_in[0];
    const float* K = (const float*)d_in[1];
    const float* V = (const float*)d_in[2];

    const long long VE = (long long)B_ * S_ * D_;
    const long long WE = (long long)B_ * S_ * S_;

    float* outVec = nullptr;
    float* outW   = nullptr;
    int writeW = 0;
    if ((long long)out_size == VE + WE) {
        outVec = (float*)d_out;
        outW   = (float*)d_out + VE;
        writeW = 1;
    } else if ((long long)out_size == WE) {
        outW   = (float*)d_out;
        writeW = 1;
    } else {
        outVec = (float*)d_out;
    }
    float* wPtr = writeW ? outW : (float*)d_out;

    cudaFuncSetAttribute(attn_tiles, cudaFuncAttributeMaxDynamicSharedMemorySize,
                         SMEM_TOTAL);

    dim3 gA(UNITS_PER_B, B_);
    attn_tiles<<<gA, 256, SMEM_TOTAL>>>(Q, K, V, wPtr, writeW);

    reduce_l<<<(B_ * S_ + 255) / 256, 256>>>();

    if (outVec)
        reduce_o<<<(B_ * S_ * (D_ / 4) + 255) / 256, 256>>>(outVec);

    if (writeW) {
        long long nf4 = WE / 4;
        norm_w<<<(unsigned)(nf4 / 256), 256>>>(outW);
    }
}

// round 12
// speedup vs baseline: 1.2422x; 1.0835x over previous
#include <cuda_runtime.h>
#include <cuda_bf16.h>
#include <cstdint>
#include <math.h>

#define B_  4
#define S_  4096
#define D_  64
#define BQ  128
#define BK  128
#define UNITS_PER_B 528
#define NUNITS     2112

/* ---------------- scratch ---------------- */
__device__ float g_Lp[(size_t)NUNITS * 128];
__device__ float g_Op[(size_t)NUNITS * 128 * 64];
__device__ float g_invL[B_ * S_];

/* preconverted operands: Q/K [b][s][32 uint32 = 64 bf16] hi/lo,
   Vt [b][d][2048 uint32 = 4096 bf16 along k] hi/lo. uint4 for alignment. */
__device__ uint4 g_Qhi[B_ * S_ * 8];
__device__ uint4 g_Qlo[B_ * S_ * 8];
__device__ uint4 g_Khi[B_ * S_ * 8];
__device__ uint4 g_Klo[B_ * S_ * 8];
__device__ uint4 g_Vthi[B_ * 64 * 512];
__device__ uint4 g_Vtlo[B_ * 64 * 512];

/* ---------------- SMEM map (bytes) ---------------- */
#define QK_STRIDE 72
#define EV_STRIDE 136
#define SM_RSUM   0
#define SM_QHI    1024
#define SM_QLO    (SM_QHI + 18432)
#define SM_KHI    (SM_QLO + 18432)
#define SM_KLO    (SM_KHI + 18432)
#define SM_VTHI   (SM_KLO + 18432)
#define SM_VTLO   (SM_VTHI + 17408)
#define SM_EHI    SM_QHI
#define SM_ELO    (SM_QHI + 34816)
#define SMEM_TOTAL (SM_VTLO + 17408)       /* 109568 B -> 2 CTAs/SM */

#define MMA16816(c, a, b0, b1) \
    asm volatile("mma.sync.aligned.m16n8k16.row.col.f32.bf16.bf16.f32 " \
        "{%0,%1,%2,%3}, {%4,%5,%6,%7}, {%8,%9}, {%0,%1,%2,%3};"         \
        : "+f"((c)[0]), "+f"((c)[1]), "+f"((c)[2]), "+f"((c)[3])        \
        : "r"((a)[0]), "r"((a)[1]), "r"((a)[2]), "r"((a)[3]),           \
          "r"(b0), "r"(b1))

__device__ __forceinline__ void bf16_split2(float f0, float f1,
                                            uint32_t& h2, uint32_t& l2) {
    asm("cvt.rn.bf16x2.f32 %0, %1, %2;" : "=r"(h2) : "f"(f1), "f"(f0));
    float h0 = __uint_as_float(h2 << 16);
    float h1 = __uint_as_float(h2 & 0xFFFF0000u);
    float r0 = f0 - h0, r1 = f1 - h1;
    asm("cvt.rn.bf16x2.f32 %0, %1, %2;" : "=r"(l2) : "f"(r1), "f"(r0));
}

__device__ __forceinline__ float fast_exp(float x) {
    float t = x * 1.4426950408889634f;
    float r = t + 12582912.0f;
    int   n = __float_as_int(r) - 0x4B400000;
    float f = t - (r - 12582912.0f);
    float p = 1.3333558e-3f;
    p = fmaf(p, f, 9.6181291e-3f);
    p = fmaf(p, f, 5.5504109e-2f);
    p = fmaf(p, f, 2.4022651e-1f);
    p = fmaf(p, f, 6.9314718e-1f);
    p = fmaf(p, f, 1.0f);
    return __int_as_float(__float_as_int(p) + (n << 23));
}

/* ------------- prep: convert Q,K to bf16 hi/lo (elementwise) ------------- */
__global__ void __launch_bounds__(256)
prep_qk(const float2* __restrict__ Qf, const float2* __restrict__ Kf)
{
    const int t = blockIdx.x * 256 + threadIdx.x;    /* 0..524287 */
    {
        float2 v = Qf[t];
        uint32_t h, l;
        bf16_split2(v.x, v.y, h, l);
        ((uint32_t*)g_Qhi)[t] = h;
        ((uint32_t*)g_Qlo)[t] = l;
    }
    {
        float2 v = Kf[t];
        uint32_t h, l;
        bf16_split2(v.x, v.y, h, l);
        ((uint32_t*)g_Khi)[t] = h;
        ((uint32_t*)g_Klo)[t] = l;
    }
}

/* ------------- prep: V -> transposed bf16 hi/lo via smem tile ------------ */
__global__ void __launch_bounds__(256)
prep_v(const float* __restrict__ V)
{
    __shared__ unsigned short sh[64][66], sl[64][66];
    const int kt64 = blockIdx.x;    /* 0..63: 64-row k chunk */
    const int b    = blockIdx.y;
    const int tid  = threadIdx.x;
    const float* Vb = V + ((size_t)b * S_ + kt64 * 64) * D_;

#pragma unroll
    for (int it = 0; it < 16; it++) {
        const int idx = tid + it * 256;          /* 0..4095 */
        const int k = idx >> 6, d = idx & 63;
        float v = Vb[k * D_ + d];
        __nv_bfloat16 h = __float2bfloat16(v);
        __nv_bfloat16 l = __float2bfloat16(v - __bfloat162float(h));
        sh[d][k] = __bfloat16_as_ushort(h);
        sl[d][k] = __bfloat16_as_ushort(l);
    }
    __syncthreads();
#pragma unroll
    for (int it = 0; it < 8; it++) {
        const int idx = tid + it * 256;          /* 0..2047 */
        const int d = idx >> 5, ku = idx & 31;
        uint32_t uh = (uint32_t)sh[d][2 * ku] | ((uint32_t)sh[d][2 * ku + 1] << 16);
        uint32_t ul = (uint32_t)sl[d][2 * ku] | ((uint32_t)sl[d][2 * ku + 1] << 16);
        const size_t o = ((size_t)(b * 64 + d)) * 2048 + kt64 * 32 + ku;
        ((uint32_t*)g_Vthi)[o] = uh;
        ((uint32_t*)g_Vtlo)[o] = ul;
    }
}

/* ------------------------------------------------------------------ */
/* Kernel A: one (qt,kt) 128x128 unit per CTA; preconverted operands. */
/* Also zero-fills its mirror upper-triangle W tile (kt<qt).          */
/* ------------------------------------------------------------------ */
__global__ void __launch_bounds__(256, 2)
attn_tiles(float* __restrict__ outW, int writeW)
{
    extern __shared__ char smx[];

    const int tid = threadIdx.x;
    const int wid = tid >> 5;
    const int lid = tid & 31;
    const int g   = lid >> 2;
    const int tg  = lid & 3;
    const int wr  = wid & 3;
    const int wc  = wid >> 2;

    const int b = blockIdx.y;
    const int x = blockIdx.x;
    int qt = (int)((sqrtf(8.0f * (float)x + 1.0f) - 1.0f) * 0.5f);
    while ((qt + 1) * (qt + 2) / 2 <= x) qt++;
    while (qt * (qt + 1) / 2 > x) qt--;
    const int kt   = x - qt * (qt + 1) / 2;
    const int unit = b * UNITS_PER_B + x;
    const bool diag = (qt == kt);

    /* ---- fill Q/K smem from preconverted arrays: uint4 copy ---- */
    const uint4* Qh4 = g_Qhi + ((size_t)b * S_ + (size_t)qt * BQ) * 8;
    const uint4* Ql4 = g_Qlo + ((size_t)b * S_ + (size_t)qt * BQ) * 8;
    const uint4* Kh4 = g_Khi + ((size_t)b * S_ + (size_t)kt * BK) * 8;
    const uint4* Kl4 = g_Klo + ((size_t)b * S_ + (size_t)kt * BK) * 8;
#pragma unroll
    for (int it = 0; it < 4; it++) {
        const int idx = tid + it * 256;          /* 0..1023 */
        const int row = idx >> 3, c = idx & 7;
        const int so = row * 144 + c * 16;
        *(uint4*)(smx + SM_QHI + so) = Qh4[idx];
        *(uint4*)(smx + SM_QLO + so) = Ql4[idx];
        *(uint4*)(smx + SM_KHI + so) = Kh4[idx];
        *(uint4*)(smx + SM_KLO + so) = Kl4[idx];
    }
    /* ---- fill Vt smem: [64 d][136 bf16-pairs], uint4 copy ---- */
    const uint4* Vh4 = g_Vthi + (size_t)b * 64 * 512 + kt * 16;
    const uint4* Vl4 = g_Vtlo + (size_t)b * 64 * 512 + kt * 16;
#pragma unroll
    for (int it = 0; it < 4; it++) {
        const int idx = tid + it * 256;          /* 0..1023 */
        const int d = idx >> 4, c = idx & 15;
        const int so = d * 272 + c * 16;
        const size_t go = (size_t)d * 512 + c;
        *(uint4*)(smx + SM_VTHI + so) = Vh4[go];
        *(uint4*)(smx + SM_VTLO + so) = Vl4[go];
    }
    /* ---- zero-fill mirror upper tile (overlaps with compute) ---- */
    if (writeW && kt < qt) {
        float* Zt = outW + ((size_t)(b * S_ + kt * BK)) * S_ + (size_t)qt * BQ;
        float4 z; z.x = z.y = z.z = z.w = 0.0f;
#pragma unroll
        for (int it = 0; it < 16; it++) {
            const int f = tid + it * 256;        /* 0..4095 */
            const int row = f >> 5, c4 = f & 31;
            *(float4*)(Zt + (size_t)row * S_ + 4 * c4) = z;
        }
    }
    __syncthreads();

    /* ================= QK^T: warp tile 32 x 64 ================= */
    float c[2][8][4];
#pragma unroll
    for (int t = 0; t < 2; t++)
#pragma unroll
        for (int j = 0; j < 8; j++)
#pragma unroll
            for (int r = 0; r < 4; r++) c[t][j][r] = 0.0f;

#pragma unroll
    for (int pp = 0; pp < 3; pp++) {
        const char* Ab = smx + ((pp == 2) ? SM_QLO : SM_QHI);
        const char* Bb = smx + ((pp == 1) ? SM_KLO : SM_KHI);
#pragma unroll
        for (int ks = 0; ks < 4; ks++) {
            uint32_t a[2][4];
#pragma unroll
            for (int t = 0; t < 2; t++) {
                const int base = (32 * wr + 16 * t + g) * QK_STRIDE + 16 * ks + 2 * tg;
                a[t][0] = *(const uint32_t*)(Ab + 2 * base);
                a[t][1] = *(const uint32_t*)(Ab + 2 * (base + 8 * QK_STRIDE));
                a[t][2] = *(const uint32_t*)(Ab + 2 * (base + 8));
                a[t][3] = *(const uint32_t*)(Ab + 2 * (base + 8 * QK_STRIDE + 8));
            }
#pragma unroll
            for (int j = 0; j < 8; j++) {
                const int cb = (64 * wc + 8 * j + g) * QK_STRIDE + 16 * ks + 2 * tg;
                uint32_t b0 = *(const uint32_t*)(Bb + 2 * cb);
                uint32_t b1 = *(const uint32_t*)(Bb + 2 * (cb + 8));
                MMA16816(c[0][j], a[0], b0, b1);
                MMA16816(c[1][j], a[1], b0, b1);
            }
        }
    }
    __syncthreads();   /* K reads done; E (aliases Q/K) writable */

    /* ======== epilogue: mask+exp, E split to smem, row sums ======== */
    float rs[2][2] = {{0.0f, 0.0f}, {0.0f, 0.0f}};
#pragma unroll
    for (int t = 0; t < 2; t++) {
#pragma unroll
        for (int u = 0; u < 2; u++) {
            const int row = 32 * wr + 16 * t + 8 * u + g;
#pragma unroll
            for (int j = 0; j < 8; j++) {
                const int cb = 64 * wc + 8 * j + 2 * tg;
                float s0 = c[t][j][2 * u]     * 0.125f;
                float s1 = c[t][j][2 * u + 1] * 0.125f;
                float e0 = (diag && (cb     > row)) ? 0.0f : fast_exp(s0);
                float e1 = (diag && (cb + 1 > row)) ? 0.0f : fast_exp(s1);
                rs[t][u] += e0 + e1;
                uint32_t h2, l2;
                bf16_split2(e0, e1, h2, l2);
                const int eoff = (row * EV_STRIDE + cb) * 2;
                *(uint32_t*)(smx + SM_EHI + eoff) = h2;
                *(uint32_t*)(smx + SM_ELO + eoff) = l2;
            }
        }
    }
#pragma unroll
    for (int t = 0; t < 2; t++)
#pragma unroll
        for (int u = 0; u < 2; u++) {
            float v = rs[t][u];
            v += __shfl_xor_sync(0xffffffffu, v, 1);
            v += __shfl_xor_sync(0xffffffffu, v, 2);
            if (tg == 0) {
                const int row = 32 * wr + 16 * t + 8 * u + g;
                ((float*)(smx + SM_RSUM))[row * 2 + wc] = v;
            }
        }
    __syncthreads();

    if (tid < 128) {
        const float* r = (const float*)(smx + SM_RSUM);
        g_Lp[(size_t)unit * 128 + tid] = r[2 * tid] + r[2 * tid + 1];
    }

    /* ================= O = E @ V: warp tile 32 x 32 ================= */
    float o[2][4][4];
#pragma unroll
    for (int t = 0; t < 2; t++)
#pragma unroll
        for (int j = 0; j < 4; j++)
#pragma unroll
            for (int r = 0; r < 4; r++) o[t][j][r] = 0.0f;

#pragma unroll
    for (int pp = 0; pp < 3; pp++) {
        const char* Ab = smx + ((pp == 2) ? SM_ELO : SM_EHI);
        const char* Bb = smx + ((pp == 1) ? SM_VTLO : SM_VTHI);
#pragma unroll
        for (int ks = 0; ks < 8; ks++) {
            uint32_t a[2][4];
#pragma unroll
            for (int t = 0; t < 2; t++) {
                const int base = (32 * wr + 16 * t + g) * EV_STRIDE + 16 * ks + 2 * tg;
                a[t][0] = *(const uint32_t*)(Ab + 2 * base);
                a[t][1] = *(const uint32_t*)(Ab + 2 * (base + 8 * EV_STRIDE));
                a[t][2] = *(const uint32_t*)(Ab + 2 * (base + 8));
                a[t][3] = *(const uint32_t*)(Ab + 2 * (base + 8 * EV_STRIDE + 8));
            }
#pragma unroll
            for (int j = 0; j < 4; j++) {
                const int cb = (32 * wc + 8 * j + g) * EV_STRIDE + 16 * ks + 2 * tg;
                uint32_t b0 = *(const uint32_t*)(Bb + 2 * cb);
                uint32_t b1 = *(const uint32_t*)(Bb + 2 * (cb + 8));
                MMA16816(o[0][j], a[0], b0, b1);
                MMA16816(o[1][j], a[1], b0, b1);
            }
        }
    }

    /* ---- coalesced W store: reconstruct e = hi + lo from E smem ---- */
    if (writeW) {
        float* Wt = outW + ((size_t)(b * S_ + qt * BQ)) * S_ + (size_t)kt * BK;
#pragma unroll
        for (int it = 0; it < 16; it++) {
            const int f   = tid + it * 256;
            const int row = f >> 5, c4 = f & 31;
            const int eo  = (row * EV_STRIDE + 4 * c4) * 2;
            uint32_t h0 = *(const uint32_t*)(smx + SM_EHI + eo);
            uint32_t l0 = *(const uint32_t*)(smx + SM_ELO + eo);
            uint32_t h1 = *(const uint32_t*)(smx + SM_EHI + eo + 4);
            uint32_t l1 = *(const uint32_t*)(smx + SM_ELO + eo + 4);
            float4 w;
            w.x = __uint_as_float(h0 << 16)         + __uint_as_float(l0 << 16);
            w.y = __uint_as_float(h0 & 0xFFFF0000u) + __uint_as_float(l0 & 0xFFFF0000u);
            w.z = __uint_as_float(h1 << 16)         + __uint_as_float(l1 << 16);
            w.w = __uint_as_float(h1 & 0xFFFF0000u) + __uint_as_float(l1 & 0xFFFF0000u);
            *(float4*)(Wt + (size_t)row * S_ + 4 * c4) = w;
        }
    }

    /* ---- store O partials ---- */
    float* Ob = g_Op + (size_t)unit * (128 * 64);
#pragma unroll
    for (int t = 0; t < 2; t++)
#pragma unroll
        for (int u = 0; u < 2; u++) {
            const int row = 32 * wr + 16 * t + 8 * u + g;
#pragma unroll
            for (int j = 0; j < 4; j++) {
                const int cb = 32 * wc + 8 * j + 2 * tg;
                float2 w;
                w.x = o[t][j][2 * u];
                w.y = o[t][j][2 * u + 1];
                *(float2*)(Ob + (size_t)row * 64 + cb) = w;
            }
        }
}

/* ---------------- Kernel B1: invL per row ---------------- */
__global__ void __launch_bounds__(256)
reduce_l()
{
    int t = blockIdx.x * 256 + threadIdx.x;
    if (t >= B_ * S_) return;
    int b = t >> 12, q = t & (S_ - 1);
    int qt = q >> 7, i = q & 127;
    int tri = qt * (qt + 1) / 2;
    float s = 0.0f;
    for (int kt = 0; kt <= qt; kt++)
        s += g_Lp[((size_t)(b * UNITS_PER_B + tri + kt)) * 128 + i];
    g_invL[t] = 1.0f / s;
}

/* ---------------- Kernel B2: O = (sum of partials) * invL ---------------- */
__global__ void __launch_bounds__(256)
reduce_o(float* __restrict__ outV)
{
    int t = blockIdx.x * 256 + threadIdx.x;
    if (t >= B_ * S_ * (D_ / 4)) return;
    int d4 = t & 15;
    int q  = (t >> 4) & (S_ - 1);
    int b  = t >> 16;
    int qt = q >> 7, i = q & 127;
    int tri = qt * (qt + 1) / 2;
    float ax = 0.f, ay = 0.f, az = 0.f, aw = 0.f;
    for (int kt = 0; kt <= qt; kt++) {
        const float4 v = *(const float4*)(g_Op +
            ((size_t)(b * UNITS_PER_B + tri + kt) * 128 + i) * 64 + d4 * 4);
        ax += v.x; ay += v.y; az += v.z; aw += v.w;
    }
    float inv = g_invL[b * S_ + q];
    float4 r; r.x = ax * inv; r.y = ay * inv; r.z = az * inv; r.w = aw * inv;
    *(float4*)(outV + ((size_t)(b * S_ + q)) * D_ + d4 * 4) = r;
}

/* -------- Kernel C: normalize LOWER-triangle tiles only (zeros done) ----- */
__global__ void __launch_bounds__(256)
norm_w2(float* __restrict__ outW)
{
    const int x = blockIdx.x;    /* lower-tri unit 0..527 */
    const int b = blockIdx.y;
    const int tid = threadIdx.x;
    int qt = (int)((sqrtf(8.0f * (float)x + 1.0f) - 1.0f) * 0.5f);
    while ((qt + 1) * (qt + 2) / 2 <= x) qt++;
    while (qt * (qt + 1) / 2 > x) qt--;
    const int kt = x - qt * (qt + 1) / 2;

    const float* inv = g_invL + b * S_ + qt * BQ;
    float* Wt = outW + ((size_t)(b * S_ + qt * BQ)) * S_ + (size_t)kt * BK;
#pragma unroll
    for (int it = 0; it < 16; it++) {
        const int f = tid + it * 256;            /* 0..4095 float4s */
        const int row = f >> 5, c4 = f & 31;
        const float iv = inv[row];
        float4* p = (float4*)(Wt + (size_t)row * S_) + c4;
        float4 v = *p;
        v.x *= iv; v.y *= iv; v.z *= iv; v.w *= iv;
        *p = v;
    }
}

/* ------------------------------------------------------------------ */
extern "C" void kernel_launch(void* const* d_in, const int* in_sizes, int n_in,
                              void* d_out, int out_size)
{
    const float* Q = (const float*)d_in[0];
    const float* K = (const float*)d_in[1];
    const float* V = (const float*)d_in[2];

    const long long VE = (long long)B_ * S_ * D_;
    const long long WE = (long long)B_ * S_ * S_;

    float* outVec = nullptr;
    float* outW   = nullptr;
    int writeW = 0;
    if ((long long)out_size == VE + WE) {
        outVec = (float*)d_out;
        outW   = (float*)d_out + VE;
        writeW = 1;
    } else if ((long long)out_size == WE) {
        outW   = (float*)d_out;
        writeW = 1;
    } else {
        outVec = (float*)d_out;
    }
    float* wPtr = writeW ? outW : (float*)d_out;

    cudaFuncSetAttribute(attn_tiles, cudaFuncAttributeMaxDynamicSharedMemorySize,
                         SMEM_TOTAL);

    prep_qk<<<(B_ * S_ * 32) / 256, 256>>>((const float2*)Q, (const float2*)K);
    prep_v<<<dim3(64, B_), 256>>>(V);

    dim3 gA(UNITS_PER_B, B_);
    attn_tiles<<<gA, 256, SMEM_TOTAL>>>(wPtr, writeW);

    reduce_l<<<(B_ * S_ + 255) / 256, 256>>>();

    if (outVec)
        reduce_o<<<(B_ * S_ * (D_ / 4) + 255) / 256, 256>>>(outVec);

    if (writeW)
        norm_w2<<<dim3(UNITS_PER_B, B_), 256>>>(outW);
}

// round 13
// speedup vs baseline: 1.4148x; 1.1390x over previous
#include <cuda_runtime.h>
#include <cuda_bf16.h>
#include <cstdint>
#include <math.h>

#define B_  4
#define S_  4096
#define D_  64
#define BQ  128
#define BK  128
#define UNITS_PER_B 528
#define NUNITS     2112

/* ---------------- scratch ---------------- */
__device__ float g_Lp[(size_t)NUNITS * 128];
__device__ float g_Op[(size_t)NUNITS * 128 * 64];
__device__ float g_invL[B_ * S_];

/* preconverted operands */
__device__ uint4 g_Qhi[B_ * S_ * 8];
__device__ uint4 g_Qlo[B_ * S_ * 8];
__device__ uint4 g_Khi[B_ * S_ * 8];
__device__ uint4 g_Klo[B_ * S_ * 8];
__device__ uint4 g_Vthi[B_ * 64 * 512];
__device__ uint4 g_Vtlo[B_ * 64 * 512];

/* ---------------- SMEM map (bytes) ---------------- */
#define QK_STRIDE 72
#define EV_STRIDE 136
#define SM_RSUM   0
#define SM_QHI    1024
#define SM_QLO    (SM_QHI + 18432)
#define SM_KHI    (SM_QLO + 18432)
#define SM_KLO    (SM_KHI + 18432)
#define SM_VTHI   (SM_KLO + 18432)
#define SM_VTLO   (SM_VTHI + 17408)
#define SM_EHI    SM_QHI
#define SM_ELO    (SM_QHI + 34816)
#define SMEM_TOTAL (SM_VTLO + 17408)       /* 109568 B -> 2 CTAs/SM */

#define MMA16816(c, a, b0, b1) \
    asm volatile("mma.sync.aligned.m16n8k16.row.col.f32.bf16.bf16.f32 " \
        "{%0,%1,%2,%3}, {%4,%5,%6,%7}, {%8,%9}, {%0,%1,%2,%3};"         \
        : "+f"((c)[0]), "+f"((c)[1]), "+f"((c)[2]), "+f"((c)[3])        \
        : "r"((a)[0]), "r"((a)[1]), "r"((a)[2]), "r"((a)[3]),           \
          "r"(b0), "r"(b1))

__device__ __forceinline__ void bf16_split2(float f0, float f1,
                                            uint32_t& h2, uint32_t& l2) {
    asm("cvt.rn.bf16x2.f32 %0, %1, %2;" : "=r"(h2) : "f"(f1), "f"(f0));
    float h0 = __uint_as_float(h2 << 16);
    float h1 = __uint_as_float(h2 & 0xFFFF0000u);
    float r0 = f0 - h0, r1 = f1 - h1;
    asm("cvt.rn.bf16x2.f32 %0, %1, %2;" : "=r"(l2) : "f"(r1), "f"(r0));
}

__device__ __forceinline__ float fast_exp(float x) {
    float t = x * 1.4426950408889634f;
    float r = t + 12582912.0f;
    int   n = __float_as_int(r) - 0x4B400000;
    float f = t - (r - 12582912.0f);
    float p = 1.3333558e-3f;
    p = fmaf(p, f, 9.6181291e-3f);
    p = fmaf(p, f, 5.5504109e-2f);
    p = fmaf(p, f, 2.4022651e-1f);
    p = fmaf(p, f, 6.9314718e-1f);
    p = fmaf(p, f, 1.0f);
    return __int_as_float(__float_as_int(p) + (n << 23));
}

/* ------------- prep: convert Q,K to bf16 hi/lo (elementwise) ------------- */
__global__ void __launch_bounds__(256)
prep_qk(const float2* __restrict__ Qf, const float2* __restrict__ Kf)
{
    const int t = blockIdx.x * 256 + threadIdx.x;
    {
        float2 v = Qf[t];
        uint32_t h, l;
        bf16_split2(v.x, v.y, h, l);
        ((uint32_t*)g_Qhi)[t] = h;
        ((uint32_t*)g_Qlo)[t] = l;
    }
    {
        float2 v = Kf[t];
        uint32_t h, l;
        bf16_split2(v.x, v.y, h, l);
        ((uint32_t*)g_Khi)[t] = h;
        ((uint32_t*)g_Klo)[t] = l;
    }
}

/* ------------- prep: V -> transposed bf16 hi/lo via smem tile ------------ */
__global__ void __launch_bounds__(256)
prep_v(const float* __restrict__ V)
{
    __shared__ unsigned short sh[64][66], sl[64][66];
    const int kt64 = blockIdx.x;
    const int b    = blockIdx.y;
    const int tid  = threadIdx.x;
    const float* Vb = V + ((size_t)b * S_ + kt64 * 64) * D_;

#pragma unroll
    for (int it = 0; it < 16; it++) {
        const int idx = tid + it * 256;
        const int k = idx >> 6, d = idx & 63;
        float v = Vb[k * D_ + d];
        __nv_bfloat16 h = __float2bfloat16(v);
        __nv_bfloat16 l = __float2bfloat16(v - __bfloat162float(h));
        sh[d][k] = __bfloat16_as_ushort(h);
        sl[d][k] = __bfloat16_as_ushort(l);
    }
    __syncthreads();
#pragma unroll
    for (int it = 0; it < 8; it++) {
        const int idx = tid + it * 256;
        const int d = idx >> 5, ku = idx & 31;
        uint32_t uh = (uint32_t)sh[d][2 * ku] | ((uint32_t)sh[d][2 * ku + 1] << 16);
        uint32_t ul = (uint32_t)sl[d][2 * ku] | ((uint32_t)sl[d][2 * ku + 1] << 16);
        const size_t o = ((size_t)(b * 64 + d)) * 2048 + kt64 * 32 + ku;
        ((uint32_t*)g_Vthi)[o] = uh;
        ((uint32_t*)g_Vtlo)[o] = ul;
    }
}

/* ------------------------------------------------------------------ */
/* Kernel A: one (qt,kt) 128x128 unit per CTA; preconverted operands, */
/* pass-fused 3-way split MMAs; zero-fills mirror upper W tile.       */
/* ------------------------------------------------------------------ */
__global__ void __launch_bounds__(256, 2)
attn_tiles(float* __restrict__ outW, int writeW)
{
    extern __shared__ char smx[];

    const int tid = threadIdx.x;
    const int wid = tid >> 5;
    const int lid = tid & 31;
    const int g   = lid >> 2;
    const int tg  = lid & 3;
    const int wr  = wid & 3;
    const int wc  = wid >> 2;

    const int b = blockIdx.y;
    const int x = blockIdx.x;
    int qt = (int)((sqrtf(8.0f * (float)x + 1.0f) - 1.0f) * 0.5f);
    while ((qt + 1) * (qt + 2) / 2 <= x) qt++;
    while (qt * (qt + 1) / 2 > x) qt--;
    const int kt   = x - qt * (qt + 1) / 2;
    const int unit = b * UNITS_PER_B + x;
    const bool diag = (qt == kt);

    /* ---- fill Q/K smem from preconverted arrays: uint4 copy ---- */
    const uint4* Qh4 = g_Qhi + ((size_t)b * S_ + (size_t)qt * BQ) * 8;
    const uint4* Ql4 = g_Qlo + ((size_t)b * S_ + (size_t)qt * BQ) * 8;
    const uint4* Kh4 = g_Khi + ((size_t)b * S_ + (size_t)kt * BK) * 8;
    const uint4* Kl4 = g_Klo + ((size_t)b * S_ + (size_t)kt * BK) * 8;
#pragma unroll
    for (int it = 0; it < 4; it++) {
        const int idx = tid + it * 256;
        const int row = idx >> 3, c = idx & 7;
        const int so = row * 144 + c * 16;
        *(uint4*)(smx + SM_QHI + so) = Qh4[idx];
        *(uint4*)(smx + SM_QLO + so) = Ql4[idx];
        *(uint4*)(smx + SM_KHI + so) = Kh4[idx];
        *(uint4*)(smx + SM_KLO + so) = Kl4[idx];
    }
    /* ---- fill Vt smem ---- */
    const uint4* Vh4 = g_Vthi + (size_t)b * 64 * 512 + kt * 16;
    const uint4* Vl4 = g_Vtlo + (size_t)b * 64 * 512 + kt * 16;
#pragma unroll
    for (int it = 0; it < 4; it++) {
        const int idx = tid + it * 256;
        const int d = idx >> 4, c = idx & 15;
        const int so = d * 272 + c * 16;
        const size_t go = (size_t)d * 512 + c;
        *(uint4*)(smx + SM_VTHI + so) = Vh4[go];
        *(uint4*)(smx + SM_VTLO + so) = Vl4[go];
    }
    /* ---- zero-fill mirror upper tile (overlaps with compute) ---- */
    if (writeW && kt < qt) {
        float* Zt = outW + ((size_t)(b * S_ + kt * BK)) * S_ + (size_t)qt * BQ;
        float4 z; z.x = z.y = z.z = z.w = 0.0f;
#pragma unroll
        for (int it = 0; it < 16; it++) {
            const int f = tid + it * 256;
            const int row = f >> 5, c4 = f & 31;
            *(float4*)(Zt + (size_t)row * S_ + 4 * c4) = z;
        }
    }
    __syncthreads();

    /* ============ QK^T: warp tile 32 x 64, pass-fused 3-way ============ */
    float c[2][8][4];
#pragma unroll
    for (int t = 0; t < 2; t++)
#pragma unroll
        for (int j = 0; j < 8; j++)
#pragma unroll
            for (int r = 0; r < 4; r++) c[t][j][r] = 0.0f;

    {
        const char* Ah = smx + SM_QHI;
        const char* Al = smx + SM_QLO;
        const char* Bh = smx + SM_KHI;
        const char* Bl = smx + SM_KLO;
#pragma unroll
        for (int ks = 0; ks < 4; ks++) {
            uint32_t ah[2][4], al[2][4];
#pragma unroll
            for (int t = 0; t < 2; t++) {
                const int base = (32 * wr + 16 * t + g) * QK_STRIDE + 16 * ks + 2 * tg;
                ah[t][0] = *(const uint32_t*)(Ah + 2 * base);
                ah[t][1] = *(const uint32_t*)(Ah + 2 * (base + 8 * QK_STRIDE));
                ah[t][2] = *(const uint32_t*)(Ah + 2 * (base + 8));
                ah[t][3] = *(const uint32_t*)(Ah + 2 * (base + 8 * QK_STRIDE + 8));
                al[t][0] = *(const uint32_t*)(Al + 2 * base);
                al[t][1] = *(const uint32_t*)(Al + 2 * (base + 8 * QK_STRIDE));
                al[t][2] = *(const uint32_t*)(Al + 2 * (base + 8));
                al[t][3] = *(const uint32_t*)(Al + 2 * (base + 8 * QK_STRIDE + 8));
            }
#pragma unroll
            for (int j = 0; j < 8; j++) {
                const int cb = (64 * wc + 8 * j + g) * QK_STRIDE + 16 * ks + 2 * tg;
                uint32_t bh0 = *(const uint32_t*)(Bh + 2 * cb);
                uint32_t bh1 = *(const uint32_t*)(Bh + 2 * (cb + 8));
                uint32_t bl0 = *(const uint32_t*)(Bl + 2 * cb);
                uint32_t bl1 = *(const uint32_t*)(Bl + 2 * (cb + 8));
#pragma unroll
                for (int t = 0; t < 2; t++) {
                    MMA16816(c[t][j], ah[t], bh0, bh1);
                    MMA16816(c[t][j], ah[t], bl0, bl1);
                    MMA16816(c[t][j], al[t], bh0, bh1);
                }
            }
        }
    }
    __syncthreads();   /* K reads done; E (aliases Q/K) writable */

    /* ======== epilogue: mask+exp, E split to smem, row sums ======== */
    float rs[2][2] = {{0.0f, 0.0f}, {0.0f, 0.0f}};
#pragma unroll
    for (int t = 0; t < 2; t++) {
#pragma unroll
        for (int u = 0; u < 2; u++) {
            const int row = 32 * wr + 16 * t + 8 * u + g;
#pragma unroll
            for (int j = 0; j < 8; j++) {
                const int cb = 64 * wc + 8 * j + 2 * tg;
                float s0 = c[t][j][2 * u]     * 0.125f;
                float s1 = c[t][j][2 * u + 1] * 0.125f;
                float e0 = (diag && (cb     > row)) ? 0.0f : fast_exp(s0);
                float e1 = (diag && (cb + 1 > row)) ? 0.0f : fast_exp(s1);
                rs[t][u] += e0 + e1;
                uint32_t h2, l2;
                bf16_split2(e0, e1, h2, l2);
                const int eoff = (row * EV_STRIDE + cb) * 2;
                *(uint32_t*)(smx + SM_EHI + eoff) = h2;
                *(uint32_t*)(smx + SM_ELO + eoff) = l2;
            }
        }
    }
#pragma unroll
    for (int t = 0; t < 2; t++)
#pragma unroll
        for (int u = 0; u < 2; u++) {
            float v = rs[t][u];
            v += __shfl_xor_sync(0xffffffffu, v, 1);
            v += __shfl_xor_sync(0xffffffffu, v, 2);
            if (tg == 0) {
                const int row = 32 * wr + 16 * t + 8 * u + g;
                ((float*)(smx + SM_RSUM))[row * 2 + wc] = v;
            }
        }
    __syncthreads();

    if (tid < 128) {
        const float* r = (const float*)(smx + SM_RSUM);
        g_Lp[(size_t)unit * 128 + tid] = r[2 * tid] + r[2 * tid + 1];
    }

    /* ========== O = E @ V: warp tile 32 x 32, pass-fused 3-way ========== */
    float o[2][4][4];
#pragma unroll
    for (int t = 0; t < 2; t++)
#pragma unroll
        for (int j = 0; j < 4; j++)
#pragma unroll
            for (int r = 0; r < 4; r++) o[t][j][r] = 0.0f;

    {
        const char* Ah = smx + SM_EHI;
        const char* Al = smx + SM_ELO;
        const char* Bh = smx + SM_VTHI;
        const char* Bl = smx + SM_VTLO;
#pragma unroll
        for (int ks = 0; ks < 8; ks++) {
            uint32_t ah[2][4], al[2][4];
#pragma unroll
            for (int t = 0; t < 2; t++) {
                const int base = (32 * wr + 16 * t + g) * EV_STRIDE + 16 * ks + 2 * tg;
                ah[t][0] = *(const uint32_t*)(Ah + 2 * base);
                ah[t][1] = *(const uint32_t*)(Ah + 2 * (base + 8 * EV_STRIDE));
                ah[t][2] = *(const uint32_t*)(Ah + 2 * (base + 8));
                ah[t][3] = *(const uint32_t*)(Ah + 2 * (base + 8 * EV_STRIDE + 8));
                al[t][0] = *(const uint32_t*)(Al + 2 * base);
                al[t][1] = *(const uint32_t*)(Al + 2 * (base + 8 * EV_STRIDE));
                al[t][2] = *(const uint32_t*)(Al + 2 * (base + 8));
                al[t][3] = *(const uint32_t*)(Al + 2 * (base + 8 * EV_STRIDE + 8));
            }
#pragma unroll
            for (int j = 0; j < 4; j++) {
                const int cb = (32 * wc + 8 * j + g) * EV_STRIDE + 16 * ks + 2 * tg;
                uint32_t bh0 = *(const uint32_t*)(Bh + 2 * cb);
                uint32_t bh1 = *(const uint32_t*)(Bh + 2 * (cb + 8));
                uint32_t bl0 = *(const uint32_t*)(Bl + 2 * cb);
                uint32_t bl1 = *(const uint32_t*)(Bl + 2 * (cb + 8));
#pragma unroll
                for (int t = 0; t < 2; t++) {
                    MMA16816(o[t][j], ah[t], bh0, bh1);
                    MMA16816(o[t][j], ah[t], bl0, bl1);
                    MMA16816(o[t][j], al[t], bh0, bh1);
                }
            }
        }
    }

    /* ---- coalesced W store: reconstruct e = hi + lo from E smem ---- */
    if (writeW) {
        float* Wt = outW + ((size_t)(b * S_ + qt * BQ)) * S_ + (size_t)kt * BK;
#pragma unroll
        for (int it = 0; it < 16; it++) {
            const int f   = tid + it * 256;
            const int row = f >> 5, c4 = f & 31;
            const int eo  = (row * EV_STRIDE + 4 * c4) * 2;
            uint32_t h0 = *(const uint32_t*)(smx + SM_EHI + eo);
            uint32_t l0 = *(const uint32_t*)(smx + SM_ELO + eo);
            uint32_t h1 = *(const uint32_t*)(smx + SM_EHI + eo + 4);
            uint32_t l1 = *(const uint32_t*)(smx + SM_ELO + eo + 4);
            float4 w;
            w.x = __uint_as_float(h0 << 16)         + __uint_as_float(l0 << 16);
            w.y = __uint_as_float(h0 & 0xFFFF0000u) + __uint_as_float(l0 & 0xFFFF0000u);
            w.z = __uint_as_float(h1 << 16)         + __uint_as_float(l1 << 16);
            w.w = __uint_as_float(h1 & 0xFFFF0000u) + __uint_as_float(l1 & 0xFFFF0000u);
            *(float4*)(Wt + (size_t)row * S_ + 4 * c4) = w;
        }
    }

    /* ---- store O partials ---- */
    float* Ob = g_Op + (size_t)unit * (128 * 64);
#pragma unroll
    for (int t = 0; t < 2; t++)
#pragma unroll
        for (int u = 0; u < 2; u++) {
            const int row = 32 * wr + 16 * t + 8 * u + g;
#pragma unroll
            for (int j = 0; j < 4; j++) {
                const int cb = 32 * wc + 8 * j + 2 * tg;
                float2 w;
                w.x = o[t][j][2 * u];
                w.y = o[t][j][2 * u + 1];
                *(float2*)(Ob + (size_t)row * 64 + cb) = w;
            }
        }
}

/* ---------------- Kernel B1: invL per row (4 threads/row) ---------------- */
__global__ void __launch_bounds__(256)
reduce_l()
{
    int t = blockIdx.x * 256 + threadIdx.x;      /* 0..65535 */
    int p = t & 3;
    int r = t >> 2;                              /* 0..16383 */
    int b = r >> 12, q = r & (S_ - 1);
    int qt = q >> 7, i = q & 127;
    int tri = qt * (qt + 1) / 2;
    float s = 0.0f;
    for (int kt = p; kt <= qt; kt += 4)
        s += g_Lp[((size_t)(b * UNITS_PER_B + tri + kt)) * 128 + i];
    s += __shfl_xor_sync(0xffffffffu, s, 1);
    s += __shfl_xor_sync(0xffffffffu, s, 2);
    if (p == 0) g_invL[r] = 1.0f / s;
}

/* ---------------- Kernel B2: O = (sum of partials) * invL ---------------- */
__global__ void __launch_bounds__(256)
reduce_o(float* __restrict__ outV)
{
    int t = blockIdx.x * 256 + threadIdx.x;
    if (t >= B_ * S_ * (D_ / 4)) return;
    int d4 = t & 15;
    int q  = (t >> 4) & (S_ - 1);
    int b  = t >> 16;
    int qt = q >> 7, i = q & 127;
    int tri = qt * (qt + 1) / 2;
    float ax = 0.f, ay = 0.f, az = 0.f, aw = 0.f;
    for (int kt = 0; kt <= qt; kt++) {
        const float4 v = *(const float4*)(g_Op +
            ((size_t)(b * UNITS_PER_B + tri + kt) * 128 + i) * 64 + d4 * 4);
        ax += v.x; ay += v.y; az += v.z; aw += v.w;
    }
    float inv = g_invL[b * S_ + q];
    float4 r; r.x = ax * inv; r.y = ay * inv; r.z = az * inv; r.w = aw * inv;
    *(float4*)(outV + ((size_t)(b * S_ + q)) * D_ + d4 * 4) = r;
}

/* -------- Kernel C: normalize LOWER-triangle tiles only ----------------- */
__global__ void __launch_bounds__(256)
norm_w2(float* __restrict__ outW)
{
    const int x = blockIdx.x;
    const int b = blockIdx.y;
    const int tid = threadIdx.x;
    int qt = (int)((sqrtf(8.0f * (float)x + 1.0f) - 1.0f) * 0.5f);
    while ((qt + 1) * (qt + 2) / 2 <= x) qt++;
    while (qt * (qt + 1) / 2 > x) qt--;
    const int kt = x - qt * (qt + 1) / 2;

    const float* inv = g_invL + b * S_ + qt * BQ;
    float* Wt = outW + ((size_t)(b * S_ + qt * BQ)) * S_ + (size_t)kt * BK;
#pragma unroll
    for (int it = 0; it < 16; it++) {
        const int f = tid + it * 256;
        const int row = f >> 5, c4 = f & 31;
        const float iv = inv[row];
        float4* p = (float4*)(Wt + (size_t)row * S_) + c4;
        float4 v = *p;
        v.x *= iv; v.y *= iv; v.z *= iv; v.w *= iv;
        *p = v;
    }
}

/* ------------------------------------------------------------------ */
extern "C" void kernel_launch(void* const* d_in, const int* in_sizes, int n_in,
                              void* d_out, int out_size)
{
    const float* Q = (const float*)d_in[0];
    const float* K = (const float*)d_in[1];
    const float* V = (const float*)d_in[2];

    const long long VE = (long long)B_ * S_ * D_;
    const long long WE = (long long)B_ * S_ * S_;

    float* outVec = nullptr;
    float* outW   = nullptr;
    int writeW = 0;
    if ((long long)out_size == VE + WE) {
        outVec = (float*)d_out;
        outW   = (float*)d_out + VE;
        writeW = 1;
    } else if ((long long)out_size == WE) {
        outW   = (float*)d_out;
        writeW = 1;
    } else {
        outVec = (float*)d_out;
    }
    float* wPtr = writeW ? outW : (float*)d_out;

    cudaFuncSetAttribute(attn_tiles, cudaFuncAttributeMaxDynamicSharedMemorySize,
                         SMEM_TOTAL);

    prep_qk<<<(B_ * S_ * 32) / 256, 256>>>((const float2*)Q, (const float2*)K);
    prep_v<<<dim3(64, B_), 256>>>(V);

    dim3 gA(UNITS_PER_B, B_);
    attn_tiles<<<gA, 256, SMEM_TOTAL>>>(wPtr, writeW);

    reduce_l<<<(B_ * S_ * 4) / 256, 256>>>();

    if (outVec)
        reduce_o<<<(B_ * S_ * (D_ / 4) + 255) / 256, 256>>>(outVec);

    if (writeW)
        norm_w2<<<dim3(UNITS_PER_B, B_), 256>>>(outW);
}

// round 16
// speedup vs baseline: 1.4771x; 1.0440x over previous
#include <cuda_runtime.h>
#include <cuda_bf16.h>
#include <cstdint>
#include <math.h>

#define B_  4
#define S_  4096
#define D_  64
#define BQ  128
#define BK  128
#define UNITS_PER_B 528
#define NUNITS     2112

/* ---------------- accumulators (L2-resident) ---------------- */
__device__ float  g_L[B_ * S_];            /* 64 KB  */
__device__ float4 g_O4[B_ * S_ * D_ / 4];  /* 4 MB   */

/* preconverted operands */
__device__ uint4 g_Qhi[B_ * S_ * 8];
__device__ uint4 g_Qlo[B_ * S_ * 8];
__device__ uint4 g_Khi[B_ * S_ * 8];
__device__ uint4 g_Klo[B_ * S_ * 8];
__device__ uint4 g_Vthi[B_ * 64 * 512];
__device__ uint4 g_Vtlo[B_ * 64 * 512];

/* ---------------- SMEM map (bytes) ---------------- */
#define QK_STRIDE 72
#define EV_STRIDE 136
#define SM_QHI    1024
#define SM_QLO    (SM_QHI + 18432)
#define SM_KHI    (SM_QLO + 18432)
#define SM_KLO    (SM_KHI + 18432)
#define SM_VTHI   (SM_KLO + 18432)
#define SM_VTLO   (SM_VTHI + 17408)
#define SM_EHI    SM_QHI
#define SM_ELO    (SM_QHI + 34816)
#define SMEM_TOTAL (SM_VTLO + 17408)       /* 109568 B -> 2 CTAs/SM */

#define MMA16816(c, a, b0, b1) \
    asm volatile("mma.sync.aligned.m16n8k16.row.col.f32.bf16.bf16.f32 " \
        "{%0,%1,%2,%3}, {%4,%5,%6,%7}, {%8,%9}, {%0,%1,%2,%3};"         \
        : "+f"((c)[0]), "+f"((c)[1]), "+f"((c)[2]), "+f"((c)[3])        \
        : "r"((a)[0]), "r"((a)[1]), "r"((a)[2]), "r"((a)[3]),           \
          "r"(b0), "r"(b1))

__device__ __forceinline__ void bf16_split2(float f0, float f1,
                                            uint32_t& h2, uint32_t& l2) {
    asm("cvt.rn.bf16x2.f32 %0, %1, %2;" : "=r"(h2) : "f"(f1), "f"(f0));
    float h0 = __uint_as_float(h2 << 16);
    float h1 = __uint_as_float(h2 & 0xFFFF0000u);
    float r0 = f0 - h0, r1 = f1 - h1;
    asm("cvt.rn.bf16x2.f32 %0, %1, %2;" : "=r"(l2) : "f"(r1), "f"(r0));
}

__device__ __forceinline__ float fast_exp(float x) {
    float t = x * 1.4426950408889634f;
    float r = t + 12582912.0f;
    int   n = __float_as_int(r) - 0x4B400000;
    float f = t - (r - 12582912.0f);
    float p = 1.3333558e-3f;
    p = fmaf(p, f, 9.6181291e-3f);
    p = fmaf(p, f, 5.5504109e-2f);
    p = fmaf(p, f, 2.4022651e-1f);
    p = fmaf(p, f, 6.9314718e-1f);
    p = fmaf(p, f, 1.0f);
    return __int_as_float(__float_as_int(p) + (n << 23));
}

/* ------ prep: convert Q,K to bf16 hi/lo; zero L/O accumulators ------ */
__global__ void __launch_bounds__(256)
prep_qk(const float2* __restrict__ Qf, const float2* __restrict__ Kf)
{
    const int t = blockIdx.x * 256 + threadIdx.x;   /* 0..524287 */
    {
        float2 v = Qf[t];
        uint32_t h, l;
        bf16_split2(v.x, v.y, h, l);
        ((uint32_t*)g_Qhi)[t] = h;
        ((uint32_t*)g_Qlo)[t] = l;
    }
    {
        float2 v = Kf[t];
        uint32_t h, l;
        bf16_split2(v.x, v.y, h, l);
        ((uint32_t*)g_Khi)[t] = h;
        ((uint32_t*)g_Klo)[t] = l;
    }
    if (t < B_ * S_) g_L[t] = 0.0f;
    if (t < B_ * S_ * D_ / 4) {
        float4 z; z.x = z.y = z.z = z.w = 0.0f;
        g_O4[t] = z;
    }
}

/* ------------- prep: V -> transposed bf16 hi/lo via smem tile ------------ */
__global__ void __launch_bounds__(256)
prep_v(const float* __restrict__ V)
{
    __shared__ unsigned short sh[64][66], sl[64][66];
    const int kt64 = blockIdx.x;
    const int b    = blockIdx.y;
    const int tid  = threadIdx.x;
    const float* Vb = V + ((size_t)b * S_ + kt64 * 64) * D_;

#pragma unroll
    for (int it = 0; it < 16; it++) {
        const int idx = tid + it * 256;
        const int k = idx >> 6, d = idx & 63;
        float v = Vb[k * D_ + d];
        __nv_bfloat16 h = __float2bfloat16(v);
        __nv_bfloat16 l = __float2bfloat16(v - __bfloat162float(h));
        sh[d][k] = __bfloat16_as_ushort(h);
        sl[d][k] = __bfloat16_as_ushort(l);
    }
    __syncthreads();
#pragma unroll
    for (int it = 0; it < 8; it++) {
        const int idx = tid + it * 256;
        const int d = idx >> 5, ku = idx & 31;
        uint32_t uh = (uint32_t)sh[d][2 * ku] | ((uint32_t)sh[d][2 * ku + 1] << 16);
        uint32_t ul = (uint32_t)sl[d][2 * ku] | ((uint32_t)sl[d][2 * ku + 1] << 16);
        const size_t o = ((size_t)(b * 64 + d)) * 2048 + kt64 * 32 + ku;
        ((uint32_t*)g_Vthi)[o] = uh;
        ((uint32_t*)g_Vtlo)[o] = ul;
    }
}

/* ------------------------------------------------------------------ */
/* Kernel A: one (qt,kt) 128x128 unit per CTA; atomics for L and O.   */
/* ------------------------------------------------------------------ */
__global__ void __launch_bounds__(256, 2)
attn_tiles(float* __restrict__ outW, int writeW, int accumV)
{
    extern __shared__ char smx[];

    const int tid = threadIdx.x;
    const int wid = tid >> 5;
    const int lid = tid & 31;
    const int g   = lid >> 2;
    const int tg  = lid & 3;
    const int wr  = wid & 3;
    const int wc  = wid >> 2;

    const int b = blockIdx.y;
    const int x = blockIdx.x;
    int qt = (int)((sqrtf(8.0f * (float)x + 1.0f) - 1.0f) * 0.5f);
    while ((qt + 1) * (qt + 2) / 2 <= x) qt++;
    while (qt * (qt + 1) / 2 > x) qt--;
    const int kt   = x - qt * (qt + 1) / 2;
    const bool diag = (qt == kt);

    /* ---- fill Q/K smem from preconverted arrays: uint4 copy ---- */
    const uint4* Qh4 = g_Qhi + ((size_t)b * S_ + (size_t)qt * BQ) * 8;
    const uint4* Ql4 = g_Qlo + ((size_t)b * S_ + (size_t)qt * BQ) * 8;
    const uint4* Kh4 = g_Khi + ((size_t)b * S_ + (size_t)kt * BK) * 8;
    const uint4* Kl4 = g_Klo + ((size_t)b * S_ + (size_t)kt * BK) * 8;
#pragma unroll
    for (int it = 0; it < 4; it++) {
        const int idx = tid + it * 256;
        const int row = idx >> 3, c = idx & 7;
        const int so = row * 144 + c * 16;
        *(uint4*)(smx + SM_QHI + so) = Qh4[idx];
        *(uint4*)(smx + SM_QLO + so) = Ql4[idx];
        *(uint4*)(smx + SM_KHI + so) = Kh4[idx];
        *(uint4*)(smx + SM_KLO + so) = Kl4[idx];
    }
    /* ---- fill Vt smem ---- */
    const uint4* Vh4 = g_Vthi + (size_t)b * 64 * 512 + kt * 16;
    const uint4* Vl4 = g_Vtlo + (size_t)b * 64 * 512 + kt * 16;
#pragma unroll
    for (int it = 0; it < 4; it++) {
        const int idx = tid + it * 256;
        const int d = idx >> 4, c = idx & 15;
        const int so = d * 272 + c * 16;
        const size_t go = (size_t)d * 512 + c;
        *(uint4*)(smx + SM_VTHI + so) = Vh4[go];
        *(uint4*)(smx + SM_VTLO + so) = Vl4[go];
    }
    /* ---- zero-fill mirror upper tile (overlaps with compute) ---- */
    if (writeW && kt < qt) {
        float* Zt = outW + ((size_t)(b * S_ + kt * BK)) * S_ + (size_t)qt * BQ;
        float4 z; z.x = z.y = z.z = z.w = 0.0f;
#pragma unroll
        for (int it = 0; it < 16; it++) {
            const int f = tid + it * 256;
            const int row = f >> 5, c4 = f & 31;
            *(float4*)(Zt + (size_t)row * S_ + 4 * c4) = z;
        }
    }
    __syncthreads();

    /* ============ QK^T: warp tile 32 x 64, pass-fused 3-way ============ */
    float c[2][8][4];
#pragma unroll
    for (int t = 0; t < 2; t++)
#pragma unroll
        for (int j = 0; j < 8; j++)
#pragma unroll
            for (int r = 0; r < 4; r++) c[t][j][r] = 0.0f;

    {
        const char* Ah = smx + SM_QHI;
        const char* Al = smx + SM_QLO;
        const char* Bh = smx + SM_KHI;
        const char* Bl = smx + SM_KLO;
#pragma unroll
        for (int ks = 0; ks < 4; ks++) {
            uint32_t ah[2][4], al[2][4];
#pragma unroll
            for (int t = 0; t < 2; t++) {
                const int base = (32 * wr + 16 * t + g) * QK_STRIDE + 16 * ks + 2 * tg;
                ah[t][0] = *(const uint32_t*)(Ah + 2 * base);
                ah[t][1] = *(const uint32_t*)(Ah + 2 * (base + 8 * QK_STRIDE));
                ah[t][2] = *(const uint32_t*)(Ah + 2 * (base + 8));
                ah[t][3] = *(const uint32_t*)(Ah + 2 * (base + 8 * QK_STRIDE + 8));
                al[t][0] = *(const uint32_t*)(Al + 2 * base);
                al[t][1] = *(const uint32_t*)(Al + 2 * (base + 8 * QK_STRIDE));
                al[t][2] = *(const uint32_t*)(Al + 2 * (base + 8));
                al[t][3] = *(const uint32_t*)(Al + 2 * (base + 8 * QK_STRIDE + 8));
            }
#pragma unroll
            for (int j = 0; j < 8; j++) {
                const int cb = (64 * wc + 8 * j + g) * QK_STRIDE + 16 * ks + 2 * tg;
                uint32_t bh0 = *(const uint32_t*)(Bh + 2 * cb);
                uint32_t bh1 = *(const uint32_t*)(Bh + 2 * (cb + 8));
                uint32_t bl0 = *(const uint32_t*)(Bl + 2 * cb);
                uint32_t bl1 = *(const uint32_t*)(Bl + 2 * (cb + 8));
#pragma unroll
                for (int t = 0; t < 2; t++) {
                    MMA16816(c[t][j], ah[t], bh0, bh1);
                    MMA16816(c[t][j], ah[t], bl0, bl1);
                    MMA16816(c[t][j], al[t], bh0, bh1);
                }
            }
        }
    }
    __syncthreads();   /* K reads done; E (aliases Q/K) writable */

    /* ======== epilogue: mask+exp, E split to smem, row-sum atomics ======== */
#pragma unroll
    for (int t = 0; t < 2; t++) {
#pragma unroll
        for (int u = 0; u < 2; u++) {
            const int row = 32 * wr + 16 * t + 8 * u + g;
            float rs = 0.0f;
#pragma unroll
            for (int j = 0; j < 8; j++) {
                const int cb = 64 * wc + 8 * j + 2 * tg;
                float s0 = c[t][j][2 * u]     * 0.125f;
                float s1 = c[t][j][2 * u + 1] * 0.125f;
                float e0 = (diag && (cb     > row)) ? 0.0f : fast_exp(s0);
                float e1 = (diag && (cb + 1 > row)) ? 0.0f : fast_exp(s1);
                rs += e0 + e1;
                uint32_t h2, l2;
                bf16_split2(e0, e1, h2, l2);
                const int eoff = (row * EV_STRIDE + cb) * 2;
                *(uint32_t*)(smx + SM_EHI + eoff) = h2;
                *(uint32_t*)(smx + SM_ELO + eoff) = l2;
            }
            rs += __shfl_xor_sync(0xffffffffu, rs, 1);
            rs += __shfl_xor_sync(0xffffffffu, rs, 2);
            if (tg == 0)
                atomicAdd(&g_L[b * S_ + qt * BQ + row], rs);
        }
    }
    __syncthreads();   /* E visible */

    /* ========== O = E @ V: warp tile 32 x 32, pass-fused 3-way ========== */
    if (accumV) {
        float o[2][4][4];
#pragma unroll
        for (int t = 0; t < 2; t++)
#pragma unroll
            for (int j = 0; j < 4; j++)
#pragma unroll
                for (int r = 0; r < 4; r++) o[t][j][r] = 0.0f;

        const char* Ah = smx + SM_EHI;
        const char* Al = smx + SM_ELO;
        const char* Bh = smx + SM_VTHI;
        const char* Bl = smx + SM_VTLO;
#pragma unroll
        for (int ks = 0; ks < 8; ks++) {
            uint32_t ah[2][4], al[2][4];
#pragma unroll
            for (int t = 0; t < 2; t++) {
                const int base = (32 * wr + 16 * t + g) * EV_STRIDE + 16 * ks + 2 * tg;
                ah[t][0] = *(const uint32_t*)(Ah + 2 * base);
                ah[t][1] = *(const uint32_t*)(Ah + 2 * (base + 8 * EV_STRIDE));
                ah[t][2] = *(const uint32_t*)(Ah + 2 * (base + 8));
                ah[t][3] = *(const uint32_t*)(Ah + 2 * (base + 8 * EV_STRIDE + 8));
                al[t][0] = *(const uint32_t*)(Al + 2 * base);
                al[t][1] = *(const uint32_t*)(Al + 2 * (base + 8 * EV_STRIDE));
                al[t][2] = *(const uint32_t*)(Al + 2 * (base + 8));
                al[t][3] = *(const uint32_t*)(Al + 2 * (base + 8 * EV_STRIDE + 8));
            }
#pragma unroll
            for (int j = 0; j < 4; j++) {
                const int cb = (32 * wc + 8 * j + g) * EV_STRIDE + 16 * ks + 2 * tg;
                uint32_t bh0 = *(const uint32_t*)(Bh + 2 * cb);
                uint32_t bh1 = *(const uint32_t*)(Bh + 2 * (cb + 8));
                uint32_t bl0 = *(const uint32_t*)(Bl + 2 * cb);
                uint32_t bl1 = *(const uint32_t*)(Bl + 2 * (cb + 8));
#pragma unroll
                for (int t = 0; t < 2; t++) {
                    MMA16816(o[t][j], ah[t], bh0, bh1);
                    MMA16816(o[t][j], ah[t], bl0, bl1);
                    MMA16816(o[t][j], al[t], bh0, bh1);
                }
            }
        }

        /* accumulate O partials via REDG into L2-resident g_O */
        float* gO = (float*)g_O4;
#pragma unroll
        for (int t = 0; t < 2; t++)
#pragma unroll
            for (int u = 0; u < 2; u++) {
                const int row = 32 * wr + 16 * t + 8 * u + g;
                float* orow = gO + ((size_t)(b * S_ + qt * BQ + row)) * D_;
#pragma unroll
                for (int j = 0; j < 4; j++) {
                    const int cb = 32 * wc + 8 * j + 2 * tg;
                    atomicAdd(orow + cb,     o[t][j][2 * u]);
                    atomicAdd(orow + cb + 1, o[t][j][2 * u + 1]);
                }
            }
    }

    /* ---- coalesced W store: reconstruct e = hi + lo from E smem ---- */
    if (writeW) {
        float* Wt = outW + ((size_t)(b * S_ + qt * BQ)) * S_ + (size_t)kt * BK;
#pragma unroll
        for (int it = 0; it < 16; it++) {
            const int f   = tid + it * 256;
            const int row = f >> 5, c4 = f & 31;
            const int eo  = (row * EV_STRIDE + 4 * c4) * 2;
            uint32_t h0 = *(const uint32_t*)(smx + SM_EHI + eo);
            uint32_t l0 = *(const uint32_t*)(smx + SM_ELO + eo);
            uint32_t h1 = *(const uint32_t*)(smx + SM_EHI + eo + 4);
            uint32_t l1 = *(const uint32_t*)(smx + SM_ELO + eo + 4);
            float4 w;
            w.x = __uint_as_float(h0 << 16)         + __uint_as_float(l0 << 16);
            w.y = __uint_as_float(h0 & 0xFFFF0000u) + __uint_as_float(l0 & 0xFFFF0000u);
            w.z = __uint_as_float(h1 << 16)         + __uint_as_float(l1 << 16);
            w.w = __uint_as_float(h1 & 0xFFFF0000u) + __uint_as_float(l1 & 0xFFFF0000u);
            *(float4*)(Wt + (size_t)row * S_ + 4 * c4) = w;
        }
    }
}

/* ---------------- finalize: outV = g_O / L ---------------- */
__global__ void __launch_bounds__(256)
finalize_o(float* __restrict__ outV)
{
    int t = blockIdx.x * 256 + threadIdx.x;     /* float4 id, 0..262143 */
    int q  = (t >> 4) & (S_ - 1);
    int b  = t >> 16;
    float inv = 1.0f / g_L[b * S_ + q];
    float4 v = g_O4[t];
    v.x *= inv; v.y *= inv; v.z *= inv; v.w *= inv;
    ((float4*)outV)[t] = v;
}

/* -------- norm_w2: normalize LOWER-triangle tiles only ----------------- */
__global__ void __launch_bounds__(256)
norm_w2(float* __restrict__ outW)
{
    __shared__ float sInv[128];
    const int x = blockIdx.x;
    const int b = blockIdx.y;
    const int tid = threadIdx.x;
    int qt = (int)((sqrtf(8.0f * (float)x + 1.0f) - 1.0f) * 0.5f);
    while ((qt + 1) * (qt + 2) / 2 <= x) qt++;
    while (qt * (qt + 1) / 2 > x) qt--;
    const int kt = x - qt * (qt + 1) / 2;

    if (tid < 128) sInv[tid] = 1.0f / g_L[b * S_ + qt * BQ + tid];
    __syncthreads();

    float* Wt = outW + ((size_t)(b * S_ + qt * BQ)) * S_ + (size_t)kt * BK;
#pragma unroll
    for (int it = 0; it < 16; it++) {
        const int f = tid + it * 256;
        const int row = f >> 5, c4 = f & 31;
        const float iv = sInv[row];
        float4* p = (float4*)(Wt + (size_t)row * S_) + c4;
        float4 v = *p;
        v.x *= iv; v.y *= iv; v.z *= iv; v.w *= iv;
        *p = v;
    }
}

/* ------------------------------------------------------------------ */
extern "C" void kernel_launch(void* const* d_in, const int* in_sizes, int n_in,
                              void* d_out, int out_size)
{
    const float* Q = (const float*)d_in[0];
    const float* K = (const float*)d_in[1];
    const float* V = (const float*)d_in[2];

    const long long VE = (long long)B_ * S_ * D_;
    const long long WE = (long long)B_ * S_ * S_;

    float* outVec = nullptr;
    float* outW   = nullptr;
    int writeW = 0;
    if ((long long)out_size == VE + WE) {
        outVec = (float*)d_out;
        outW   = (float*)d_out + VE;
        writeW = 1;
    } else if ((long long)out_size == WE) {
        outW   = (float*)d_out;
        writeW = 1;
    } else {
        outVec = (float*)d_out;
    }
    float* wPtr = writeW ? outW : (float*)d_out;

    cudaFuncSetAttribute(attn_tiles, cudaFuncAttributeMaxDynamicSharedMemorySize,
                         SMEM_TOTAL);

    prep_qk<<<(B_ * S_ * 32) / 256, 256>>>((const float2*)Q, (const float2*)K);
    prep_v<<<dim3(64, B_), 256>>>(V);

    dim3 gA(UNITS_PER_B, B_);
    attn_tiles<<<gA, 256, SMEM_TOTAL>>>(wPtr, writeW, outVec != nullptr);

    if (outVec)
        finalize_o<<<(B_ * S_ * (D_ / 4)) / 256, 256>>>(outVec);

    if (writeW)
        norm_w2<<<dim3(UNITS_PER_B, B_), 256>>>(outW);
}